// round 8
// baseline (speedup 1.0000x reference)
#include <cuda_runtime.h>
#include <cuda_fp16.h>
#include <cstdint>

#define NTOK 65536
#define MT 64
#define MAXTILE 1040
#define NSM 148

// byte offsets in dynamic smem
#define SM_X    0         // 64*68 half2 = 17408 B (pad 68 words/row)
#define SM_B    17408     // 131072 B single weight buffer (one layer, one expert)
#define SM_PQ   148480    // P: 64x132 f32 (33792 B), Q follows
#define SM_BIAS 216064    // 512 floats (this layer)
#define SM_TOK  218112    // 64 ints
#define SMEM_MAIN 218368

__device__ int g_cnt[9];
__device__ int g_ntiles;
__device__ int g_done;
__device__ int g_tok[9 * NTOK];
__device__ int g_te[MAXTILE], g_ts[MAXTILE], g_tn[MAXTILE];
// fragment-ordered fp16 weights: per (l,e): 32768 words
// word = ks*4096 + g*1024 + nh*512 + ntp*128 + lane*4 + q   (ks = 0..7)
__device__ __align__(16) uint32_t g_Wf[18 * 32768];
// layer-0 output, fp16 pairs, tile-major: [tile][r(64)][c2(64)]
__device__ __align__(16) uint32_t g_Xmid[(size_t)MAXTILE * 4096];

__device__ __forceinline__ float tanha(float x) {
    float r; asm("tanh.approx.f32 %0,%1;" : "=f"(r) : "f"(x)); return r;
}
__device__ __forceinline__ float sigf(float v) {
    return fmaf(0.5f, tanha(0.5f * v), 0.5f);
}
__device__ __forceinline__ void mma16(float* c, const uint32_t* a, uint32_t b0, uint32_t b1) {
    asm volatile(
        "mma.sync.aligned.m16n8k16.row.col.f32.f16.f16.f32 "
        "{%0,%1,%2,%3},{%4,%5,%6,%7},{%8,%9},{%0,%1,%2,%3};"
        : "+f"(c[0]), "+f"(c[1]), "+f"(c[2]), "+f"(c[3])
        : "r"(a[0]), "r"(a[1]), "r"(a[2]), "r"(a[3]), "r"(b0), "r"(b1));
}
__device__ __forceinline__ uint32_t sptr(const void* p) {
    return (uint32_t)__cvta_generic_to_shared(p);
}
__device__ __forceinline__ void cpa16(uint32_t dst, const void* src) {
    asm volatile("cp.async.cg.shared.global [%0],[%1],16;" :: "r"(dst), "l"(src));
}
__device__ __forceinline__ uint32_t packh2(float a, float b) {
    __half2 h = __floats2half2_rn(a, b);
    return *(uint32_t*)&h;
}

// ---------------- prep ----------------
// grid (72, 4): CTA (m, kg) writes ks = 2kg, 2kg+1 of matrix m in fragment order
__global__ void k_wprep(const float* __restrict__ W) {
    __shared__ float s[32 * 128];
    int m = blockIdx.x, kg = blockIdx.y;
    if (m == 0 && kg == 0) {
        if (threadIdx.x < 9) g_cnt[threadIdx.x] = 0;
        if (threadIdx.x == 9) g_done = 0;
    }
    int l = m / 36, g = (m / 9) % 4, e = m % 9;
    const float* src = W + (size_t)m * 16384 + kg * 32 * 128;
    for (int i = threadIdx.x; i < 4096; i += 512) s[i] = src[i];
    __syncthreads();
    uint32_t* dst = g_Wf + (size_t)(l * 9 + e) * 32768 + g * 1024;
    for (int i = threadIdx.x; i < 2048; i += 512) {
        int ksl = i >> 10, nh = (i >> 9) & 1;
        int ntp = (i >> 7) & 3, lane = (i >> 2) & 31, q = i & 3;
        int tig = lane & 3, grp = lane >> 2, bsel = q & 1;
        int n = nh * 64 + (ntp * 2 + (q >> 1)) * 8 + grp;
        int k0l = ksl * 16 + bsel * 8 + 2 * tig;
        dst[(kg * 2 + ksl) * 4096 + nh * 512 + ntp * 128 + lane * 4 + q] =
            packh2(s[k0l * 128 + n], s[(k0l + 1) * 128 + n]);
    }
}

__global__ void k_hist(const int* __restrict__ pos) {
    __shared__ int scnt[9], sbase[9];
    __shared__ int amlast;
    int tid = threadIdx.x;
    int t = blockIdx.x * 256 + tid;
    if (tid < 9) scnt[tid] = 0;
    int probe = t & 8191;
    int bad = (pos[2 * probe + 1] != 0);
    bad = __syncthreads_or(bad);
    int p = bad ? pos[t] : pos[2 * t];
    int e = p > 8 ? 8 : (p < 0 ? 0 : p);
    int my = atomicAdd(&scnt[e], 1);
    __syncthreads();
    if (tid < 9) sbase[tid] = atomicAdd(&g_cnt[tid], scnt[tid]);
    __syncthreads();
    g_tok[e * NTOK + sbase[e] + my] = t;
    __threadfence();
    __syncthreads();
    if (tid == 0) amlast = (atomicAdd(&g_done, 1) == 255);
    __syncthreads();
    if (amlast) {
        __shared__ int ts[10];
        if (tid == 0) {
            ts[0] = 0;
            for (int ee = 0; ee < 9; ee++) ts[ee + 1] = ts[ee] + ((g_cnt[ee] + MT - 1) / MT);
            g_ntiles = ts[9];
        }
        __syncthreads();
        int n = ts[9];
        for (int tt = tid; tt < n; tt += 256) {
            int ee = 0;
            while (!(tt >= ts[ee] && tt < ts[ee + 1])) ee++;
            int s = (tt - ts[ee]) * MT;
            g_te[tt] = ee; g_ts[tt] = s;
            int rem = g_cnt[ee] - s;
            g_tn[tt] = rem < MT ? rem : MT;
        }
    }
}

// ---------------- per-layer persistent kernel ----------------
template<int L>
__global__ void __launch_bounds__(1024, 1)
k_layer(const float* __restrict__ xin, const float* __restrict__ bs, float* __restrict__ out) {
    extern __shared__ __align__(16) char smc[];
    int tid = threadIdx.x, lane = tid & 31, w = tid >> 5;
    int g = w >> 3, mh = (w >> 1) & 3, nh = w & 1;
    int tig = lane & 3, grp = lane >> 2;

    uint32_t* Xs2 = (uint32_t*)smc;
    float* P = (float*)(smc + SM_PQ);
    float* Q = P + 64 * 132;
    float* sbias = (float*)(smc + SM_BIAS);
    int* stok = (int*)(smc + SM_TOK);

    int nt = g_ntiles;
    int cid = blockIdx.x;
    int base = nt / NSM, rem = nt % NSM;
    int t0 = cid * base + (cid < rem ? cid : rem);
    int cnt = base + (cid < rem ? 1 : 0);

    int cur_e = -1;
    for (int ti = 0; ti < cnt; ti++) {
        int t = t0 + ti;
        int e = g_te[t], s0 = g_ts[t], nr = g_tn[t];
        bool sw = (e != cur_e);
        cur_e = e;
        if (sw) {
            // stage this (layer, expert)'s 128 KB weight block
            const uint4* ws = (const uint4*)(g_Wf + (size_t)(L * 9 + e) * 32768);
            uint32_t d = sptr(smc + SM_B);
            #pragma unroll
            for (int i = 0; i < 8; i++)
                cpa16(d + (tid + i * 1024) * 16, ws + tid + i * 1024);
            asm volatile("cp.async.commit_group;");
            if (tid < 512)
                sbias[tid] = bs[((L * 4 + (tid >> 7)) * 9 + e) * 128 + (tid & 127)];
        }
        if (tid < MT) stok[tid] = (tid < nr) ? g_tok[e * NTOK + s0 + tid] : -1;
        __syncthreads();    // stok visible

        // load X tile into fp16 smem (pad 68 words/row)
        if (L == 0) {
            for (int i = tid; i < MT * 32; i += 1024) {
                int r = i >> 5, c4 = i & 31;
                int tk = stok[r];
                float4 v = (tk >= 0) ? ((const float4*)xin)[(size_t)tk * 32 + c4]
                                     : make_float4(0.f, 0.f, 0.f, 0.f);
                Xs2[r * 68 + c4 * 2]     = packh2(v.x, v.y);
                Xs2[r * 68 + c4 * 2 + 1] = packh2(v.z, v.w);
            }
        } else {
            uint4 v = ((const uint4*)g_Xmid)[(size_t)t * 1024 + tid];
            int r = tid >> 4, c8 = tid & 15;
            *(uint4*)(Xs2 + r * 68 + c8 * 4) = v;
        }
        if (sw) asm volatile("cp.async.wait_group 0;");
        __syncthreads();    // X + B + bias ready

        // mainloop: no internal syncs (B resident)
        float acc[8][4];
        #pragma unroll
        for (int ntc = 0; ntc < 8; ntc++)
            #pragma unroll
            for (int j = 0; j < 4; j++) acc[ntc][j] = 0.f;

        const char* bsb = smc + SM_B + g * 4096 + nh * 2048 + lane * 16;
        #pragma unroll
        for (int ks = 0; ks < 8; ks++) {
            const uint32_t* xr = Xs2 + (mh * 16 + grp) * 68 + ks * 8 + tig;
            uint32_t a[4];
            a[0] = xr[0]; a[1] = xr[8 * 68]; a[2] = xr[4]; a[3] = xr[8 * 68 + 4];
            #pragma unroll
            for (int ntp = 0; ntp < 4; ntp++) {
                uint4 b = *(const uint4*)(bsb + ks * 16384 + ntp * 512);
                mma16(acc[2 * ntp],     a, b.x, b.y);
                mma16(acc[2 * ntp + 1], a, b.z, b.w);
            }
        }

        #define FRAG_LOOP(BODY) \
            _Pragma("unroll") for (int ntc = 0; ntc < 8; ntc++) \
            _Pragma("unroll") for (int j = 0; j < 4; j++) { \
                int r = mh * 16 + grp + ((j >> 1) << 3); \
                int c = nh * 64 + ntc * 8 + tig * 2 + (j & 1); \
                float v = acc[ntc][j] + sbias[g * 128 + c]; \
                (void)v; BODY }

        if (g == 0) {
            FRAG_LOOP(
                uint32_t xp = Xs2[r * 68 + (c >> 1)];
                __half2 xh = *(__half2*)&xp;
                float xv = (c & 1) ? __half2float(__high2half(xh)) : __half2float(__low2half(xh));
                P[r * 132 + c] = xv * sigf(v);
            )
        } else if (g == 1) {
            FRAG_LOOP( Q[r * 132 + c] = tanha(v); )
        }
        __syncthreads();
        if (g == 2) {
            FRAG_LOOP( P[r * 132 + c] += Q[r * 132 + c] * sigf(v); )
        }
        __syncthreads();
        if (g == 3) {
            FRAG_LOOP( Q[r * 132 + c] = tanha(P[r * 132 + c]) * sigf(v); )
        }
        __syncthreads();

        // writeback
        if (L == 0) {
            int r = tid >> 4, c2 = (tid & 15) * 4;
            const float* qr = Q + r * 132 + 2 * c2;
            uint4 o;
            o.x = packh2(qr[0], qr[1]);
            o.y = packh2(qr[2], qr[3]);
            o.z = packh2(qr[4], qr[5]);
            o.w = packh2(qr[6], qr[7]);
            ((uint4*)g_Xmid)[(size_t)t * 1024 + tid] = o;
        } else {
            for (int i = tid; i < MT * 32; i += 1024) {
                int r = i >> 5, c4 = i & 31;
                int tk = stok[r];
                if (tk >= 0)
                    ((float4*)out)[(size_t)tk * 32 + c4] = *(float4*)&Q[r * 132 + c4 * 4];
            }
        }
        __syncthreads();    // tile done; safe to overwrite stok/X next iter
        #undef FRAG_LOOP
    }
}

extern "C" void kernel_launch(void* const* d_in, const int* in_sizes, int n_in,
                              void* d_out, int out_size) {
    const int* pos = (const int*)d_in[0];
    const float* x = (const float*)d_in[1];
    const float* W = (const float*)d_in[2];
    const float* b = (const float*)d_in[3];
    float* out = (float*)d_out;
    (void)in_sizes; (void)n_in; (void)out_size;
    cudaFuncSetAttribute(k_layer<0>, cudaFuncAttributeMaxDynamicSharedMemorySize, SMEM_MAIN);
    cudaFuncSetAttribute(k_layer<1>, cudaFuncAttributeMaxDynamicSharedMemorySize, SMEM_MAIN);
    k_wprep<<<dim3(72, 4), 512>>>(W);
    k_hist<<<256, 256>>>(pos);
    k_layer<0><<<NSM, 1024, SMEM_MAIN>>>(x, b, out);
    k_layer<1><<<NSM, 1024, SMEM_MAIN>>>(x, b, out);
}